// round 13
// baseline (speedup 1.0000x reference)
#include <cuda_runtime.h>
#include <math.h>
#include <stdint.h>

#define T_LEN 1024
#define B_SZ  64
#define H_SZ  256
#define D_SZ  256
#define C4    1024          // 4*H, col = j*4 + k (gates of a neuron contiguous)
#define NRC   128           // recurrent CTAs, 2 neurons (8 gate cols) each
#define HS_STRIDE 72        // padded word stride for h rows [d][b] (gmem + smem)
#define FLAG_STR 8          // 32B padding between flags
#define CHUNK_BYTES (32 * HS_STRIDE * 4)   // 9216B: 32 h-rows per warp chunk

// ---------------- scratch (static device allocations only) ----------------
__device__ float g_M2[D_SZ * C4];            // folded x-projection  [d][col]
__device__ float g_bias2[C4];
__device__ float g_Wp[H_SZ * C4];            // folded recurrent (Wh - We)
__device__ float g_Z[(size_t)B_SZ * T_LEN * C4];   // b-major: [b*T+t][1024]
__device__ __align__(16) float g_hT[2][H_SZ * HS_STRIDE]; // h [d][b] stride-72, dbl buf
__device__ unsigned g_flagv[NRC * FLAG_STR]; // per-CTA progress flags

// ---------------- primitives ----------------------------------------------
__device__ __forceinline__ unsigned ld_acq(const void* p) {
    unsigned v;
    asm volatile("ld.acquire.gpu.b32 %0, [%1];" : "=r"(v) : "l"(p) : "memory");
    return v;
}
__device__ __forceinline__ void st_rel(void* p, unsigned v) {
    asm volatile("st.release.gpu.b32 [%0], %1;" :: "l"(p), "r"(v) : "memory");
}
__device__ __forceinline__ uint32_t smem_u32(const void* p) {
    uint32_t a;
    asm("{ .reg .u64 t; cvta.to.shared.u64 t, %1; cvt.u32.u64 %0, t; }"
        : "=r"(a) : "l"(p));
    return a;
}
__device__ __forceinline__ void mbar_init(uint32_t mbar, uint32_t cnt) {
    asm volatile("mbarrier.init.shared.b64 [%0], %1;" :: "r"(mbar), "r"(cnt)
                 : "memory");
}
__device__ __forceinline__ void mbar_expect_tx(uint32_t mbar, uint32_t bytes) {
    asm volatile("mbarrier.arrive.expect_tx.shared.b64 _, [%0], %1;"
                 :: "r"(mbar), "r"(bytes) : "memory");
}
__device__ __forceinline__ void bulk_g2s(uint32_t dst, const void* src,
                                         uint32_t bytes, uint32_t mbar) {
    asm volatile(
        "cp.async.bulk.shared::cluster.global.mbarrier::complete_tx::bytes "
        "[%0], [%1], %2, [%3];"
        :: "r"(dst), "l"(src), "r"(bytes), "r"(mbar) : "memory");
}
__device__ __forceinline__ void mbar_wait(uint32_t mbar, uint32_t parity) {
    asm volatile(
        "{\n\t"
        ".reg .pred P;\n\t"
        "W_%=:\n\t"
        "mbarrier.try_wait.parity.acquire.cta.shared::cta.b64 P, [%0], %1;\n\t"
        "@P bra.uni D_%=;\n\t"
        "bra.uni W_%=;\n\t"
        "D_%=:\n\t"
        "}"
        :: "r"(mbar), "r"(parity) : "memory");
}
__device__ __forceinline__ unsigned f2tf32(float x) {
    unsigned r;
    asm("cvt.rna.tf32.f32 %0, %1;" : "=r"(r) : "f"(x));
    return r;
}
__device__ __forceinline__ void mma_tf32(float* c, const unsigned* a,
                                         unsigned b0, unsigned b1) {
    asm volatile(
        "mma.sync.aligned.m16n8k8.row.col.f32.tf32.tf32.f32 "
        "{%0,%1,%2,%3}, {%4,%5,%6,%7}, {%8,%9}, {%0,%1,%2,%3};"
        : "+f"(c[0]), "+f"(c[1]), "+f"(c[2]), "+f"(c[3])
        : "r"(a[0]), "r"(a[1]), "r"(a[2]), "r"(a[3]), "r"(b0), "r"(b1));
}

// ---------------- prep kernels --------------------------------------------
__global__ void k_prepM(const float* __restrict__ Win, const float* __restrict__ Wx,
                        const float* __restrict__ We, const float* __restrict__ b) {
    int k = blockIdx.x, d = blockIdx.y, j = threadIdx.x;
    float acc = Wx[(k * D_SZ + d) * H_SZ + j];
    const float* wrow = &Win[d * H_SZ];
#pragma unroll 8
    for (int e = 0; e < H_SZ; e++)
        acc = fmaf(__ldg(&wrow[e]), __ldg(&We[(k * H_SZ + e) * H_SZ + j]), acc);
    g_M2[d * C4 + j * 4 + k] = acc;
    if (d == 0) g_bias2[j * 4 + k] = b[k * H_SZ + j];
}

__global__ void k_prepW(const float* __restrict__ Wh, const float* __restrict__ We) {
    int k = blockIdx.x, h = blockIdx.y, j = threadIdx.x;
    int src = (k * H_SZ + h) * H_SZ + j;
    g_Wp[h * C4 + j * 4 + k] = Wh[src] - We[src];
}

__global__ void k_reset() {
    g_flagv[threadIdx.x] = 0;
    __threadfence();
}

// ---------------- tiled fp32 GEMM with bias (proven ~60% FFMA) -------------
template<int BN>
__global__ void __launch_bounds__(256) k_gemm_bias(
    const float* __restrict__ A, const float* __restrict__ Bm,
    const float* __restrict__ bias, float* __restrict__ Cm,
    int N, int K)
{
    const int BM = 128, BK = 16, TM = 8, TN = 4;
    __shared__ float As[BK][BM + 4];
    __shared__ float Bs[BK][BN + 4];

    int tid = threadIdx.x;
    int tx = tid % (BN / TN);
    int ty = tid / (BN / TN);
    int row0 = blockIdx.y * BM;
    int col0 = blockIdx.x * BN;

    float acc[TM][TN];
#pragma unroll
    for (int m = 0; m < TM; m++)
#pragma unroll
        for (int n = 0; n < TN; n++) acc[m][n] = 0.f;

    for (int k0 = 0; k0 < K; k0 += BK) {
#pragma unroll
        for (int i = tid; i < BM * (BK / 4); i += 256) {
            int r  = i >> 2;
            int c4 = i & 3;
            float4 v = *(const float4*)&A[(size_t)(row0 + r) * K + k0 + c4 * 4];
            As[c4 * 4 + 0][r] = v.x;
            As[c4 * 4 + 1][r] = v.y;
            As[c4 * 4 + 2][r] = v.z;
            As[c4 * 4 + 3][r] = v.w;
        }
#pragma unroll
        for (int i = tid; i < BK * (BN / 4); i += 256) {
            int r  = i / (BN / 4);
            int c4 = i % (BN / 4);
            *(float4*)&Bs[r][c4 * 4] =
                *(const float4*)&Bm[(size_t)(k0 + r) * N + col0 + c4 * 4];
        }
        __syncthreads();

#pragma unroll
        for (int k = 0; k < BK; k++) {
            float a[TM], bb[TN];
#pragma unroll
            for (int m = 0; m < TM; m++) a[m] = As[k][ty * TM + m];
#pragma unroll
            for (int n = 0; n < TN; n++) bb[n] = Bs[k][tx * TN + n];
#pragma unroll
            for (int m = 0; m < TM; m++)
#pragma unroll
                for (int n = 0; n < TN; n++)
                    acc[m][n] = fmaf(a[m], bb[n], acc[m][n]);
        }
        __syncthreads();
    }

    float4 bv = *(const float4*)&bias[col0 + tx * TN];
#pragma unroll
    for (int m = 0; m < TM; m++) {
        int r = row0 + ty * TM + m;
        float4 o;
        o.x = acc[m][0] + bv.x;
        o.y = acc[m][1] + bv.y;
        o.z = acc[m][2] + bv.z;
        o.w = acc[m][3] + bv.w;
        *(float4*)&Cm[(size_t)r * N + col0 + tx * TN] = o;
    }
}

// ---------------- phase B: persistent recurrence, bulk-copy staging --------
// 128 CTAs, 2 neurons (8 gate cols) each. h lives in GMEM in the padded
// [d][b] stride-72 layout; per step each warp bulk-copies its 16 producers'
// 9216B chunk into smem via cp.async.bulk (UBLKCP: no L1tex wavefronts, no
// cvt/STS) as soon as those producers' flags pass. mma consumes raw fp32
// bits as tf32 (HW truncation). mbarrier (count 8, tx 73728B/step) completes.
__global__ void __launch_bounds__(256, 1) k_recur(
    const float* __restrict__ h_prev, const float* __restrict__ c_prev,
    float* __restrict__ hseq, float* __restrict__ cseq)
{
    extern __shared__ float sm[];
    float* hs = sm;                          // 256*72 floats (73728B)
    float* pp = sm + H_SZ * HS_STRIDE;       // 2*64*12 floats
    uint64_t* mbar64 = (uint64_t*)(sm + H_SZ * HS_STRIDE + 2 * B_SZ * 12);
    const uint32_t mbar = smem_u32(mbar64);
    const uint32_t hs_base = smem_u32(hs);

    const int tid  = threadIdx.x;
    const int cta  = blockIdx.x;
    const int lane = tid & 31;
    const int w    = tid >> 5;
    const int mt   = w & 3;                // m-tile: rows [mt*16, +16)
    const int kh   = w >> 2;               // k-half: d in [kh*128, +128)
    const int b0   = mt * 16;
    const int dbase = kh * 128;
    const int lq = lane >> 2;              // 0..7
    const int lr = lane & 3;               // 0..3

    // Wp B-fragments (8 cols), register-resident for all steps (RNA-rounded)
    unsigned bf0[16], bf1[16];
#pragma unroll
    for (int ks = 0; ks < 16; ks++) {
        int d = dbase + ks * 8;
        int c0 = cta * 8 + lq;
        bf0[ks] = f2tf32(g_Wp[(d + lr)     * C4 + c0]);
        bf1[ks] = f2tf32(g_Wp[(d + 4 + lr) * C4 + c0]);
    }

    // init h state in padded layout: this CTA's 2 neuron rows
    if (tid < 128) {
        int jl = tid >> 6, bb = tid & 63;
        g_hT[0][(cta * 2 + jl) * HS_STRIDE + bb] =
            h_prev[bb * H_SZ + cta * 2 + jl];
    }

    // gate threads (tid < 128): own (b, local neuron)
    const int gb  = tid >> 1;
    const int gjl = tid & 1;
    const int gj  = cta * 2 + gjl;
    float creg = 0.f;
    if (tid < 128) creg = c_prev[gb * H_SZ + gj];

    if (tid == 0) mbar_init(mbar, 8);      // 8 warp-chunk arrivals per step
    __syncthreads();
    if (tid == 0) { __threadfence(); st_rel(&g_flagv[cta * FLAG_STR], 1u); }

    // each lane polls one producer flag (2 lanes per flag); warp w covers
    // producers [16w, 16w+16) whose h rows form chunk [32w, 32w+32)
    const unsigned* myflag = &g_flagv[(w * 16 + (lane & 15)) * FLAG_STR];

    for (int t = 0; t < T_LEN; t++) {
        const int par = t & 1;

        // Z prefetch (independent; overlaps the wait)
        float4 z = make_float4(0.f, 0.f, 0.f, 0.f);
        if (tid < 128)
            z = __ldg((const float4*)
                &g_Z[(size_t)(gb * T_LEN + t) * C4 + cta * 8 + gjl * 4]);

        // dataflow wait: this warp's 16 producers published h for step t
        {
            const unsigned need = (unsigned)(t + 1);
            while (!__all_sync(0xffffffffu, ld_acq(myflag) >= need)) { }
        }
        // issue this warp's chunk: rows [32w, 32w+32) of g_hT[par]
        if (lane == 0) {
            mbar_expect_tx(mbar, CHUNK_BYTES);
            bulk_g2s(hs_base + (unsigned)(w * CHUNK_BYTES),
                     &g_hT[par][w * 32 * HS_STRIDE], CHUNK_BYTES, mbar);
        }
        // wait for all 8 chunks (73728 bytes) to land
        mbar_wait(mbar, (unsigned)par);

        // mma over this warp's k-half; A-operands are raw fp32 (HW->tf32)
        float acc0[4] = {0.f, 0.f, 0.f, 0.f};
        float acc1[4] = {0.f, 0.f, 0.f, 0.f};
#pragma unroll
        for (int ks = 0; ks < 16; ks += 2) {
            unsigned a[4];
            {
                int d = dbase + ks * 8;
                const float* p = &hs[(d + lr) * HS_STRIDE + b0 + lq];
                a[0] = __float_as_uint(p[0]);
                a[1] = __float_as_uint(p[8]);
                a[2] = __float_as_uint(p[4 * HS_STRIDE]);
                a[3] = __float_as_uint(p[4 * HS_STRIDE + 8]);
                mma_tf32(acc0, a, bf0[ks], bf1[ks]);
            }
            {
                int d = dbase + (ks + 1) * 8;
                const float* p = &hs[(d + lr) * HS_STRIDE + b0 + lq];
                a[0] = __float_as_uint(p[0]);
                a[1] = __float_as_uint(p[8]);
                a[2] = __float_as_uint(p[4 * HS_STRIDE]);
                a[3] = __float_as_uint(p[4 * HS_STRIDE + 8]);
                mma_tf32(acc1, a, bf0[ks + 1], bf1[ks + 1]);
            }
        }
        acc0[0] += acc1[0]; acc0[1] += acc1[1];
        acc0[2] += acc1[2]; acc0[3] += acc1[3];

        // partials: row (b0+lq[,+8]), cols 2*lr, pitch 12
        {
            float* ppk = pp + kh * (B_SZ * 12);
            *(float2*)&ppk[(b0 + lq)     * 12 + lr * 2] = make_float2(acc0[0], acc0[1]);
            *(float2*)&ppk[(b0 + lq + 8) * 12 + lr * 2] = make_float2(acc0[2], acc0[3]);
        }
        __syncthreads();

        float hn = 0.f;
        if (tid < 128) {
            const float4 q0 = *(const float4*)&pp[gb * 12 + gjl * 4];
            const float4 q1 = *(const float4*)&pp[B_SZ * 12 + gb * 12 + gjl * 4];
            float p0 = q0.x + q1.x + z.x;
            float p1 = q0.y + q1.y + z.y;
            float p2 = q0.z + q1.z + z.z;
            float p3 = q0.w + q1.w + z.w;

            float f  = 1.f / (1.f + expf(-p0));
            float ig = 1.f / (1.f + expf(-p1));
            float o  = 1.f / (1.f + expf(-p2));
            float g  = tanhf(p3);
            creg = f * creg + ig * g;
            hn = o * tanhf(creg);

            // critical-path publish: 2 padded rows (512B) only
            g_hT[par ^ 1][gj * HS_STRIDE + gb] = hn;
        }
        __syncthreads();
        if (tid == 0) {
            __threadfence();
            st_rel(&g_flagv[cta * FLAG_STR], (unsigned)(t + 2));
        }
        // off-critical-path outputs (nothing reads these until phase C)
        if (tid < 128) {
            size_t off = (size_t)(gb * T_LEN + t) * H_SZ + gj;
            hseq[off] = hn;
            cseq[off] = creg;
        }
    }
}

// ---------------- launch --------------------------------------------------
extern "C" void kernel_launch(void* const* d_in, const int* in_sizes, int n_in,
                              void* d_out, int out_size) {
    const float* x    = (const float*)d_in[0];
    const float* h0   = (const float*)d_in[1];
    const float* c0   = (const float*)d_in[2];
    const float* Win  = (const float*)d_in[3];
    const float* Wx   = (const float*)d_in[4];
    const float* Wh   = (const float*)d_in[5];
    const float* We   = (const float*)d_in[6];
    const float* bb   = (const float*)d_in[7];
    const float* Wout = (const float*)d_in[8];
    const float* bout = (const float*)d_in[9];

    float* out  = (float*)d_out;
    float* yhat = out;                                   // [B,T,D]
    float* hseq = out + (size_t)B_SZ * T_LEN * D_SZ;     // [B,T,H]
    float* cseq = hseq + (size_t)B_SZ * T_LEN * H_SZ;    // [B,T,H]

    float *pM2, *pbias2, *pZ;
    cudaGetSymbolAddress((void**)&pM2,    g_M2);
    cudaGetSymbolAddress((void**)&pbias2, g_bias2);
    cudaGetSymbolAddress((void**)&pZ,     g_Z);

    // phase 0: fold weights + reset flags
    k_prepM<<<dim3(4, 256), 256>>>(Win, Wx, We, bb);
    k_prepW<<<dim3(4, 256), 256>>>(Wh, We);
    k_reset<<<1, NRC * FLAG_STR>>>();

    // phase A: Z = x * M2 + bias2      (65536 x 1024 x 256)
    k_gemm_bias<64><<<dim3(1024 / 64, 65536 / 128), 256>>>(
        x, pM2, pbias2, pZ, 1024, 256);

    // phase B: serial recurrence (128 CTAs, bulk-copy staging, tf32 mma)
    const int smemB = (H_SZ * HS_STRIDE + 2 * B_SZ * 12) * 4 + 16;  // 79888 B
    cudaFuncSetAttribute(k_recur, cudaFuncAttributeMaxDynamicSharedMemorySize,
                         smemB);
    k_recur<<<NRC, 256, smemB>>>(h0, c0, hseq, cseq);

    // phase C: y = h_seq * W_out + b_out   (65536 x 256 x 256)
    k_gemm_bias<64><<<dim3(256 / 64, 65536 / 128), 256>>>(
        hseq, Wout, bout, yhat, 256, 256);
}

// round 14
// speedup vs baseline: 1.5641x; 1.5641x over previous
#include <cuda_runtime.h>
#include <math.h>
#include <stdint.h>

#define T_LEN 1024
#define B_SZ  64
#define H_SZ  256
#define D_SZ  256
#define C4    1024          // 4*H, col = j*4 + k (gates of a neuron contiguous)

#define CLUSTER_N 8         // CTAs per cluster
#define N_CLUSTERS 4        // clusters (x16 batches each)
#define NRC (CLUSTER_N * N_CLUSTERS)   // 32 recurrent CTAs
#define BPC 16              // batches per cluster

// smem float offsets for k_recur
#define HB_PITCH 260                      // padded [b][d] row pitch
#define HB_SZ    (BPC * HB_PITCH)         // 4160 floats per h buffer
#define PP_OFF   (2 * HB_SZ)              // 8320
#define PP_PITCH 132
#define PP_SZ    (BPC * PP_PITCH)         // 2112 floats per k-half
#define EB_OFF   (PP_OFF + 2 * PP_SZ)     // 12544
#define MB_OFF   (EB_OFF + 512)           // 13056 (bytes 52224, 8B aligned)
#define SMEMB    ((MB_OFF + 4) * 4)       // 52240 bytes

// ---------------- scratch (static device allocations only) ----------------
__device__ float g_M2[D_SZ * C4];            // folded x-projection  [d][col]
__device__ float g_bias2[C4];
__device__ float g_Wp[H_SZ * C4];            // folded recurrent (Wh - We), [k][col]
__device__ float g_Z[(size_t)B_SZ * T_LEN * C4];   // b-major: [b*T+t][1024]

// ---------------- ptx helpers ----------------------------------------------
__device__ __forceinline__ uint32_t smem_u32(const void* p) {
    uint32_t a;
    asm("{ .reg .u64 t; cvta.to.shared.u64 t, %1; cvt.u32.u64 %0, t; }"
        : "=r"(a) : "l"(p));
    return a;
}
__device__ __forceinline__ uint32_t mapa_u32(uint32_t laddr, uint32_t rank) {
    uint32_t r;
    asm("mapa.shared::cluster.u32 %0, %1, %2;" : "=r"(r) : "r"(laddr), "r"(rank));
    return r;
}
__device__ __forceinline__ void st_dsmem_f2(uint32_t raddr, float x, float y) {
    asm volatile(
        "{\n\t.reg .b64 t;\n\tmov.b64 t, {%1, %2};\n\t"
        "st.shared::cluster.b64 [%0], t;\n\t}"
        :: "r"(raddr), "f"(x), "f"(y) : "memory");
}
__device__ __forceinline__ void mbar_init(uint32_t mbar, uint32_t cnt) {
    asm volatile("mbarrier.init.shared.b64 [%0], %1;" :: "r"(mbar), "r"(cnt)
                 : "memory");
}
__device__ __forceinline__ void mbar_arrive_remote(uint32_t raddr) {
    asm volatile(
        "mbarrier.arrive.release.cluster.shared::cluster.b64 _, [%0];"
        :: "r"(raddr) : "memory");
}
__device__ __forceinline__ void mbar_wait_cluster(uint32_t mbar, uint32_t parity) {
    asm volatile(
        "{\n\t"
        ".reg .pred P;\n\t"
        "W%=:\n\t"
        "mbarrier.try_wait.parity.acquire.cluster.shared::cta.b64 P, [%0], %1, 0x989680;\n\t"
        "@P bra.uni D%=;\n\t"
        "bra.uni W%=;\n\t"
        "D%=:\n\t"
        "}"
        :: "r"(mbar), "r"(parity) : "memory");
}
__device__ __forceinline__ void fence_cluster() {
    asm volatile("fence.acq_rel.cluster;" ::: "memory");
}
#define CLUSTER_SYNC() do { \
    asm volatile("barrier.cluster.arrive.aligned;" ::: "memory"); \
    asm volatile("barrier.cluster.wait.aligned;" ::: "memory"); \
} while (0)

__device__ __forceinline__ unsigned f2tf32(float x) {
    unsigned r;
    asm("cvt.rna.tf32.f32 %0, %1;" : "=r"(r) : "f"(x));
    return r;
}
__device__ __forceinline__ void mma_tf32(float* c, const unsigned* a,
                                         unsigned b0, unsigned b1) {
    asm volatile(
        "mma.sync.aligned.m16n8k8.row.col.f32.tf32.tf32.f32 "
        "{%0,%1,%2,%3}, {%4,%5,%6,%7}, {%8,%9}, {%0,%1,%2,%3};"
        : "+f"(c[0]), "+f"(c[1]), "+f"(c[2]), "+f"(c[3])
        : "r"(a[0]), "r"(a[1]), "r"(a[2]), "r"(a[3]), "r"(b0), "r"(b1));
}

__device__ __forceinline__ float fast_sigmoid(float x) {
    return 1.f / (1.f + __expf(-x));
}
__device__ __forceinline__ float fast_tanh(float x) {
    float xc = fminf(fmaxf(x, -30.f), 30.f);
    float t = __expf(-2.f * xc);
    return __fdividef(1.f - t, 1.f + t);
}

// ---------------- prep kernels --------------------------------------------
__global__ void k_prepM(const float* __restrict__ Win, const float* __restrict__ Wx,
                        const float* __restrict__ We, const float* __restrict__ b) {
    int k = blockIdx.x, d = blockIdx.y, j = threadIdx.x;
    float acc = Wx[(k * D_SZ + d) * H_SZ + j];
    const float* wrow = &Win[d * H_SZ];
#pragma unroll 8
    for (int e = 0; e < H_SZ; e++)
        acc = fmaf(__ldg(&wrow[e]), __ldg(&We[(k * H_SZ + e) * H_SZ + j]), acc);
    g_M2[d * C4 + j * 4 + k] = acc;
    if (d == 0) g_bias2[j * 4 + k] = b[k * H_SZ + j];
}

__global__ void k_prepW(const float* __restrict__ Wh, const float* __restrict__ We) {
    int k = blockIdx.x, h = blockIdx.y, j = threadIdx.x;
    int src = (k * H_SZ + h) * H_SZ + j;
    g_Wp[h * C4 + j * 4 + k] = Wh[src] - We[src];
}

// ---------------- tiled fp32 GEMM with bias (proven ~60% FFMA) -------------
template<int BN>
__global__ void __launch_bounds__(256) k_gemm_bias(
    const float* __restrict__ A, const float* __restrict__ Bm,
    const float* __restrict__ bias, float* __restrict__ Cm,
    int N, int K)
{
    const int BM = 128, BK = 16, TM = 8, TN = 4;
    __shared__ float As[BK][BM + 4];
    __shared__ float Bs[BK][BN + 4];

    int tid = threadIdx.x;
    int tx = tid % (BN / TN);
    int ty = tid / (BN / TN);
    int row0 = blockIdx.y * BM;
    int col0 = blockIdx.x * BN;

    float acc[TM][TN];
#pragma unroll
    for (int m = 0; m < TM; m++)
#pragma unroll
        for (int n = 0; n < TN; n++) acc[m][n] = 0.f;

    for (int k0 = 0; k0 < K; k0 += BK) {
#pragma unroll
        for (int i = tid; i < BM * (BK / 4); i += 256) {
            int r  = i >> 2;
            int c4 = i & 3;
            float4 v = *(const float4*)&A[(size_t)(row0 + r) * K + k0 + c4 * 4];
            As[c4 * 4 + 0][r] = v.x;
            As[c4 * 4 + 1][r] = v.y;
            As[c4 * 4 + 2][r] = v.z;
            As[c4 * 4 + 3][r] = v.w;
        }
#pragma unroll
        for (int i = tid; i < BK * (BN / 4); i += 256) {
            int r  = i / (BN / 4);
            int c4 = i % (BN / 4);
            *(float4*)&Bs[r][c4 * 4] =
                *(const float4*)&Bm[(size_t)(k0 + r) * N + col0 + c4 * 4];
        }
        __syncthreads();

#pragma unroll
        for (int k = 0; k < BK; k++) {
            float a[TM], bb[TN];
#pragma unroll
            for (int m = 0; m < TM; m++) a[m] = As[k][ty * TM + m];
#pragma unroll
            for (int n = 0; n < TN; n++) bb[n] = Bs[k][tx * TN + n];
#pragma unroll
            for (int m = 0; m < TM; m++)
#pragma unroll
                for (int n = 0; n < TN; n++)
                    acc[m][n] = fmaf(a[m], bb[n], acc[m][n]);
        }
        __syncthreads();
    }

    float4 bv = *(const float4*)&bias[col0 + tx * TN];
#pragma unroll
    for (int m = 0; m < TM; m++) {
        int r = row0 + ty * TM + m;
        float4 o;
        o.x = acc[m][0] + bv.x;
        o.y = acc[m][1] + bv.y;
        o.z = acc[m][2] + bv.z;
        o.w = acc[m][3] + bv.w;
        *(float4*)&Cm[(size_t)r * N + col0 + tx * TN] = o;
    }
}

// ---------------- phase B: cluster-local recurrence -------------------------
// 4 clusters x 8 CTAs. Cluster owns 16 batches (independent chains!);
// CTA owns 128 gate-cols (32 neurons), Wp slice in registers as tf32 frags.
// Per step: P[16b x 128c] = h[16 x 256] * Wp  via m16n8k8 tf32 mma.
// h exchange is intra-cluster DSMEM (st.shared::cluster + mbarrier),
// double-buffered in smem. No global flags, no membar.gpu, no L2 h state.
__global__ void __launch_bounds__(256, 1) __cluster_dims__(CLUSTER_N, 1, 1)
k_recur(const float* __restrict__ h_prev, const float* __restrict__ c_prev,
        float* __restrict__ hseq, float* __restrict__ cseq)
{
    extern __shared__ float sm[];
    const uint32_t smbase = smem_u32(sm);
    const uint32_t mbar   = smbase + MB_OFF * 4;

    const int tid  = threadIdx.x;
    const int rank = blockIdx.x & (CLUSTER_N - 1);
    const int cid  = blockIdx.x >> 3;          // cluster id
    const int bbase = cid * BPC;               // first global batch
    const int lane = tid & 31;
    const int w    = tid >> 5;
    const int kh   = w >> 2;                   // k-half: k in [128kh, 128kh+128)
    const int wn   = w & 3;                    // n-quarter: local cols [32wn, +32)
    const int lq = lane >> 2;                  // 0..7
    const int lr = lane & 3;                   // 0..3

    // ---- Wp fragments in registers: 16 ks x 4 ntiles x 2 = 128 regs -------
    unsigned wr0[16][4], wr1[16][4];
#pragma unroll
    for (int ks = 0; ks < 16; ks++) {
        int k0 = kh * 128 + ks * 8;
#pragma unroll
        for (int nt = 0; nt < 4; nt++) {
            int gc = rank * 128 + wn * 32 + nt * 8 + lq;
            wr0[ks][nt] = f2tf32(g_Wp[(k0 + lr)     * C4 + gc]);
            wr1[ks][nt] = f2tf32(g_Wp[(k0 + 4 + lr) * C4 + gc]);
        }
    }

    // ---- per-thread gate units: u = tid, tid+256 -> (b = u>>5, nn = u&31) --
    float creg[2];
    float4 zc[2], zn[2];
#pragma unroll
    for (int uu = 0; uu < 2; uu++) {
        int u = tid + uu * 256;
        int b = u >> 5, nn = u & 31;
        creg[uu] = c_prev[(bbase + b) * H_SZ + rank * 32 + nn];
        // stage h0 slice into export buffer
        sm[EB_OFF + b * 32 + nn] = h_prev[(bbase + b) * H_SZ + rank * 32 + nn];
        // prefetch Z(t=0)
        zc[uu] = __ldg((const float4*)
            &g_Z[(size_t)((bbase + b) * T_LEN + 0) * C4 + rank * 128 + nn * 4]);
    }

    if (tid == 0) mbar_init(mbar, CLUSTER_N);
    __syncthreads();
    CLUSTER_SYNC();   // all barriers initialized before any remote traffic

    // ---- publish h(0) into every cluster CTA's hbuf[0] ---------------------
    {
        const int p = w;   // warp w sends to peer p
#pragma unroll
        for (int q = 0; q < 8; q++) {
            int j  = lane + 32 * q;            // b64 index 0..255
            int bb = j >> 4;
            int n2 = (j & 15) * 2;
            float x0 = sm[EB_OFF + bb * 32 + n2];
            float x1 = sm[EB_OFF + bb * 32 + n2 + 1];
            uint32_t laddr = smbase + 4u * (0 * HB_SZ + bb * HB_PITCH + rank * 32 + n2);
            st_dsmem_f2(mapa_u32(laddr, (uint32_t)p), x0, x1);
        }
        fence_cluster();
        __syncthreads();
        if (tid < CLUSTER_N)
            mbar_arrive_remote(mapa_u32(mbar, (uint32_t)tid));
    }

    for (int t = 0; t < T_LEN; t++) {
        const int par = t & 1;

        // prefetch Z(t+1) before blocking (overlaps DRAM with the wait)
        if (t + 1 < T_LEN) {
#pragma unroll
            for (int uu = 0; uu < 2; uu++) {
                int u = tid + uu * 256;
                int b = u >> 5, nn = u & 31;
                zn[uu] = __ldg((const float4*)
                    &g_Z[(size_t)((bbase + b) * T_LEN + t + 1) * C4
                         + rank * 128 + nn * 4]);
            }
        }

        // wait: h(t) complete in hbuf[par] (8 arrivals)
        mbar_wait_cluster(mbar, (uint32_t)par);

        // ---- mma: P[16 x 128] over this warp's k-half ----------------------
        const float* hb = sm + par * HB_SZ;
        float acc[4][4];
#pragma unroll
        for (int nt = 0; nt < 4; nt++)
#pragma unroll
            for (int i = 0; i < 4; i++) acc[nt][i] = 0.f;

#pragma unroll
        for (int ks = 0; ks < 16; ks++) {
            int k0 = kh * 128 + ks * 8;
            const float* pa = &hb[lq * HB_PITCH + k0 + lr];
            unsigned a[4];
            a[0] = __float_as_uint(pa[0]);
            a[1] = __float_as_uint(pa[8 * HB_PITCH]);
            a[2] = __float_as_uint(pa[4]);
            a[3] = __float_as_uint(pa[8 * HB_PITCH + 4]);
            mma_tf32(acc[0], a, wr0[ks][0], wr1[ks][0]);
            mma_tf32(acc[1], a, wr0[ks][1], wr1[ks][1]);
            mma_tf32(acc[2], a, wr0[ks][2], wr1[ks][2]);
            mma_tf32(acc[3], a, wr0[ks][3], wr1[ks][3]);
        }

        // partials: pp[kh][b][col]
        {
            float* ppk = sm + PP_OFF + kh * PP_SZ;
#pragma unroll
            for (int nt = 0; nt < 4; nt++) {
                int c = wn * 32 + nt * 8 + lr * 2;
                *(float2*)&ppk[lq * PP_PITCH + c]       = make_float2(acc[nt][0], acc[nt][1]);
                *(float2*)&ppk[(lq + 8) * PP_PITCH + c] = make_float2(acc[nt][2], acc[nt][3]);
            }
        }
        __syncthreads();

        // ---- gates: 2 units per thread ------------------------------------
        float hn[2];
#pragma unroll
        for (int uu = 0; uu < 2; uu++) {
            int u = tid + uu * 256;
            int b = u >> 5, nn = u & 31;
            const float4 q0 = *(const float4*)&sm[PP_OFF + b * PP_PITCH + nn * 4];
            const float4 q1 = *(const float4*)&sm[PP_OFF + PP_SZ + b * PP_PITCH + nn * 4];
            float p0 = q0.x + q1.x + zc[uu].x;
            float p1 = q0.y + q1.y + zc[uu].y;
            float p2 = q0.z + q1.z + zc[uu].z;
            float p3 = q0.w + q1.w + zc[uu].w;

            float f  = fast_sigmoid(p0);
            float ig = fast_sigmoid(p1);
            float o  = fast_sigmoid(p2);
            float g  = fast_tanh(p3);
            creg[uu] = f * creg[uu] + ig * g;
            hn[uu] = o * fast_tanh(creg[uu]);
            sm[EB_OFF + b * 32 + nn] = hn[uu];
            zc[uu] = zn[uu];
        }
        __syncthreads();   // ebuf complete; pp reads done

        // ---- publish h(t+1) to all cluster CTAs (skip after last step) -----
        if (t + 1 < T_LEN) {
            const int nb = (t + 1) & 1;
            const int p = w;
#pragma unroll
            for (int q = 0; q < 8; q++) {
                int j  = lane + 32 * q;
                int bb = j >> 4;
                int n2 = (j & 15) * 2;
                float x0 = sm[EB_OFF + bb * 32 + n2];
                float x1 = sm[EB_OFF + bb * 32 + n2 + 1];
                uint32_t laddr = smbase + 4u * (nb * HB_SZ + bb * HB_PITCH + rank * 32 + n2);
                st_dsmem_f2(mapa_u32(laddr, (uint32_t)p), x0, x1);
            }
            fence_cluster();
            __syncthreads();
            if (tid < CLUSTER_N)
                mbar_arrive_remote(mapa_u32(mbar, (uint32_t)tid));
        }

        // off-critical-path outputs
#pragma unroll
        for (int uu = 0; uu < 2; uu++) {
            int u = tid + uu * 256;
            int b = u >> 5, nn = u & 31;
            size_t off = (size_t)((bbase + b) * T_LEN + t) * H_SZ + rank * 32 + nn;
            hseq[off] = hn[uu];
            cseq[off] = creg[uu];
        }
    }
}

// ---------------- launch --------------------------------------------------
extern "C" void kernel_launch(void* const* d_in, const int* in_sizes, int n_in,
                              void* d_out, int out_size) {
    const float* x    = (const float*)d_in[0];
    const float* h0   = (const float*)d_in[1];
    const float* c0   = (const float*)d_in[2];
    const float* Win  = (const float*)d_in[3];
    const float* Wx   = (const float*)d_in[4];
    const float* Wh   = (const float*)d_in[5];
    const float* We   = (const float*)d_in[6];
    const float* bb   = (const float*)d_in[7];
    const float* Wout = (const float*)d_in[8];
    const float* bout = (const float*)d_in[9];

    float* out  = (float*)d_out;
    float* yhat = out;                                   // [B,T,D]
    float* hseq = out + (size_t)B_SZ * T_LEN * D_SZ;     // [B,T,H]
    float* cseq = hseq + (size_t)B_SZ * T_LEN * H_SZ;    // [B,T,H]

    float *pM2, *pbias2, *pZ;
    cudaGetSymbolAddress((void**)&pM2,    g_M2);
    cudaGetSymbolAddress((void**)&pbias2, g_bias2);
    cudaGetSymbolAddress((void**)&pZ,     g_Z);

    // phase 0: fold weights
    k_prepM<<<dim3(4, 256), 256>>>(Win, Wx, We, bb);
    k_prepW<<<dim3(4, 256), 256>>>(Wh, We);

    // phase A: Z = x * M2 + bias2      (65536 x 1024 x 256)
    k_gemm_bias<64><<<dim3(1024 / 64, 65536 / 128), 256>>>(
        x, pM2, pbias2, pZ, 1024, 256);

    // phase B: cluster-local recurrence (4 clusters x 8 CTAs, DSMEM exchange)
    cudaFuncSetAttribute(k_recur, cudaFuncAttributeMaxDynamicSharedMemorySize,
                         SMEMB);
    k_recur<<<NRC, 256, SMEMB>>>(h0, c0, hseq, cseq);

    // phase C: y = h_seq * W_out + b_out   (65536 x 256 x 256)
    k_gemm_bias<64><<<dim3(256 / 64, 65536 / 128), 256>>>(
        hseq, Wout, bout, yhat, 256, 256);
}

// round 16
// speedup vs baseline: 1.8997x; 1.2146x over previous
#include <cuda_runtime.h>
#include <math.h>
#include <stdint.h>

#define T_LEN 1024
#define B_SZ  64
#define H_SZ  256
#define D_SZ  256
#define C4    1024          // 4*H, col = j*4 + k (gates of a neuron contiguous)

#define CLUSTER_N 8         // CTAs per cluster
#define N_CLUSTERS 4        // clusters (x16 batches each)
#define NRC (CLUSTER_N * N_CLUSTERS)   // 32 recurrent CTAs
#define BPC 16              // batches per cluster
#define TXB 16384           // bytes received per CTA per step (8 senders x 2KB)

// smem float offsets for k_recur
#define HB_PITCH 260                      // padded [b][d] row pitch
#define HB_SZ    (BPC * HB_PITCH)         // 4160 floats per h buffer
#define PP_OFF   (2 * HB_SZ)              // 8320
#define PP_PITCH 132
#define PP_SZ    (BPC * PP_PITCH)         // 2112 floats per k-half
#define MB_OFF   (PP_OFF + 2 * PP_SZ)     // 12544 floats (byte 50176, 8B aligned)
#define SMEMB    ((MB_OFF + 8) * 4)       // 50208 bytes (2 mbarriers)

// ---------------- scratch (static device allocations only) ----------------
__device__ float g_M2[D_SZ * C4];            // folded x-projection  [d][col]
__device__ float g_bias2[C4];
__device__ float g_Wp[H_SZ * C4];            // folded recurrent (Wh - We), [k][col]
__device__ float g_Z[(size_t)B_SZ * T_LEN * C4];   // b-major: [b*T+t][1024]

// ---------------- ptx helpers ----------------------------------------------
__device__ __forceinline__ uint32_t smem_u32(const void* p) {
    uint32_t a;
    asm("{ .reg .u64 t; cvta.to.shared.u64 t, %1; cvt.u32.u64 %0, t; }"
        : "=r"(a) : "l"(p));
    return a;
}
__device__ __forceinline__ uint32_t mapa_u32(uint32_t laddr, uint32_t rank) {
    uint32_t r;
    asm("mapa.shared::cluster.u32 %0, %1, %2;" : "=r"(r) : "r"(laddr), "r"(rank));
    return r;
}
__device__ __forceinline__ void mbar_init(uint32_t mbar, uint32_t cnt) {
    asm volatile("mbarrier.init.shared.b64 [%0], %1;" :: "r"(mbar), "r"(cnt)
                 : "memory");
}
__device__ __forceinline__ void mbar_expect_tx(uint32_t mbar, uint32_t bytes) {
    asm volatile("mbarrier.arrive.expect_tx.shared.b64 _, [%0], %1;"
                 :: "r"(mbar), "r"(bytes) : "memory");
}
// remote DSMEM store carrying its own tx-count to the remote mbarrier
__device__ __forceinline__ void st_async_f2(uint32_t raddr, float x, float y,
                                            uint32_t rmbar) {
    asm volatile(
        "{\n\t.reg .b64 t;\n\tmov.b64 t, {%1, %2};\n\t"
        "st.async.shared::cluster.mbarrier::complete_tx::bytes.b64 [%0], t, [%3];\n\t}"
        :: "r"(raddr), "f"(x), "f"(y), "r"(rmbar) : "memory");
}
__device__ __forceinline__ void mbar_wait_cluster(uint32_t mbar, uint32_t parity) {
    asm volatile(
        "{\n\t"
        ".reg .pred P;\n\t"
        "W%=:\n\t"
        "mbarrier.try_wait.parity.acquire.cluster.shared::cta.b64 P, [%0], %1, 0x989680;\n\t"
        "@P bra.uni D%=;\n\t"
        "bra.uni W%=;\n\t"
        "D%=:\n\t"
        "}"
        :: "r"(mbar), "r"(parity) : "memory");
}
#define CLUSTER_SYNC() do { \
    asm volatile("barrier.cluster.arrive.aligned;" ::: "memory"); \
    asm volatile("barrier.cluster.wait.aligned;" ::: "memory"); \
} while (0)

__device__ __forceinline__ unsigned f2tf32(float x) {
    unsigned r;
    asm("cvt.rna.tf32.f32 %0, %1;" : "=r"(r) : "f"(x));
    return r;
}
__device__ __forceinline__ void mma_tf32(float* c, const unsigned* a,
                                         unsigned b0, unsigned b1) {
    asm volatile(
        "mma.sync.aligned.m16n8k8.row.col.f32.tf32.tf32.f32 "
        "{%0,%1,%2,%3}, {%4,%5,%6,%7}, {%8,%9}, {%0,%1,%2,%3};"
        : "+f"(c[0]), "+f"(c[1]), "+f"(c[2]), "+f"(c[3])
        : "r"(a[0]), "r"(a[1]), "r"(a[2]), "r"(a[3]), "r"(b0), "r"(b1));
}

__device__ __forceinline__ float fast_sigmoid(float x) {
    return 1.f / (1.f + __expf(-x));
}
__device__ __forceinline__ float fast_tanh(float x) {
    float xc = fminf(fmaxf(x, -30.f), 30.f);
    float t = __expf(-2.f * xc);
    return __fdividef(1.f - t, 1.f + t);
}

// ---------------- prep kernels --------------------------------------------
__global__ void k_prepM(const float* __restrict__ Win, const float* __restrict__ Wx,
                        const float* __restrict__ We, const float* __restrict__ b) {
    int k = blockIdx.x, d = blockIdx.y, j = threadIdx.x;
    float acc = Wx[(k * D_SZ + d) * H_SZ + j];
    const float* wrow = &Win[d * H_SZ];
#pragma unroll 8
    for (int e = 0; e < H_SZ; e++)
        acc = fmaf(__ldg(&wrow[e]), __ldg(&We[(k * H_SZ + e) * H_SZ + j]), acc);
    g_M2[d * C4 + j * 4 + k] = acc;
    if (d == 0) g_bias2[j * 4 + k] = b[k * H_SZ + j];
}

__global__ void k_prepW(const float* __restrict__ Wh, const float* __restrict__ We) {
    int k = blockIdx.x, h = blockIdx.y, j = threadIdx.x;
    int src = (k * H_SZ + h) * H_SZ + j;
    g_Wp[h * C4 + j * 4 + k] = Wh[src] - We[src];
}

// ---------------- tiled fp32 GEMM with bias (proven ~60% FFMA) -------------
template<int BN>
__global__ void __launch_bounds__(256) k_gemm_bias(
    const float* __restrict__ A, const float* __restrict__ Bm,
    const float* __restrict__ bias, float* __restrict__ Cm,
    int N, int K)
{
    const int BM = 128, BK = 16, TM = 8, TN = 4;
    __shared__ float As[BK][BM + 4];
    __shared__ float Bs[BK][BN + 4];

    int tid = threadIdx.x;
    int tx = tid % (BN / TN);
    int ty = tid / (BN / TN);
    int row0 = blockIdx.y * BM;
    int col0 = blockIdx.x * BN;

    float acc[TM][TN];
#pragma unroll
    for (int m = 0; m < TM; m++)
#pragma unroll
        for (int n = 0; n < TN; n++) acc[m][n] = 0.f;

    for (int k0 = 0; k0 < K; k0 += BK) {
#pragma unroll
        for (int i = tid; i < BM * (BK / 4); i += 256) {
            int r  = i >> 2;
            int c4 = i & 3;
            float4 v = *(const float4*)&A[(size_t)(row0 + r) * K + k0 + c4 * 4];
            As[c4 * 4 + 0][r] = v.x;
            As[c4 * 4 + 1][r] = v.y;
            As[c4 * 4 + 2][r] = v.z;
            As[c4 * 4 + 3][r] = v.w;
        }
#pragma unroll
        for (int i = tid; i < BK * (BN / 4); i += 256) {
            int r  = i / (BN / 4);
            int c4 = i % (BN / 4);
            *(float4*)&Bs[r][c4 * 4] =
                *(const float4*)&Bm[(size_t)(k0 + r) * N + col0 + c4 * 4];
        }
        __syncthreads();

#pragma unroll
        for (int k = 0; k < BK; k++) {
            float a[TM], bb[TN];
#pragma unroll
            for (int m = 0; m < TM; m++) a[m] = As[k][ty * TM + m];
#pragma unroll
            for (int n = 0; n < TN; n++) bb[n] = Bs[k][tx * TN + n];
#pragma unroll
            for (int m = 0; m < TM; m++)
#pragma unroll
                for (int n = 0; n < TN; n++)
                    acc[m][n] = fmaf(a[m], bb[n], acc[m][n]);
        }
        __syncthreads();
    }

    float4 bv = *(const float4*)&bias[col0 + tx * TN];
#pragma unroll
    for (int m = 0; m < TM; m++) {
        int r = row0 + ty * TM + m;
        float4 o;
        o.x = acc[m][0] + bv.x;
        o.y = acc[m][1] + bv.y;
        o.z = acc[m][2] + bv.z;
        o.w = acc[m][3] + bv.w;
        *(float4*)&Cm[(size_t)r * N + col0 + tx * TN] = o;
    }
}

// ---------------- phase B: cluster recurrence with st.async exchange --------
// 4 clusters x 8 CTAs; cluster owns 16 batches, CTA owns 128 gate-cols.
// Gate outputs are published DIRECTLY from registers to all 8 cluster CTAs
// via st.async (remote store + tx on the remote mbarrier). No fence, no
// staging buffer, no arrive loop. The receive mbarrier (expect_tx = 16KB)
// doubles as the step barrier: it can't flip until every local thread has
// issued its sends, which data-depends on its pp reads.
__global__ void __launch_bounds__(256, 1) __cluster_dims__(CLUSTER_N, 1, 1)
k_recur(const float* __restrict__ h_prev, const float* __restrict__ c_prev,
        float* __restrict__ hseq, float* __restrict__ cseq)
{
    extern __shared__ float sm[];
    const uint32_t smbase = smem_u32(sm);
    const uint32_t mbar0  = smbase + MB_OFF * 4;
    const uint32_t mbar1  = mbar0 + 8;

    const int tid  = threadIdx.x;
    const int rank = blockIdx.x & (CLUSTER_N - 1);
    const int cid  = blockIdx.x >> 3;          // cluster id
    const int bbase = cid * BPC;               // first global batch
    const int lane = tid & 31;
    const int w    = tid >> 5;
    const int kh   = w >> 2;                   // k-half: k in [128kh, +128)
    const int wn   = w & 3;                    // n-quarter: local cols [32wn, +32)
    const int lq = lane >> 2;                  // 0..7
    const int lr = lane & 3;                   // 0..3

    // gate-unit mapping: thread owns (b, n2) and (b, n2+1) — adjacent pair
    const int gb = tid >> 4;                   // 0..15
    const int n2 = (tid & 15) * 2;             // 0,2,..,30

    // ---- Wp fragments in registers: 16 ks x 4 ntiles x 2 = 128 regs -------
    unsigned wr0[16][4], wr1[16][4];
#pragma unroll
    for (int ks = 0; ks < 16; ks++) {
        int k0 = kh * 128 + ks * 8;
#pragma unroll
        for (int nt = 0; nt < 4; nt++) {
            int gc = rank * 128 + wn * 32 + nt * 8 + lq;
            wr0[ks][nt] = f2tf32(g_Wp[(k0 + lr)     * C4 + gc]);
            wr1[ks][nt] = f2tf32(g_Wp[(k0 + 4 + lr) * C4 + gc]);
        }
    }

    // per-thread state: c pair, current/next Z (8 floats each)
    float2 creg = *(const float2*)&c_prev[(bbase + gb) * H_SZ + rank * 32 + n2];
    float4 zca = __ldg((const float4*)
        &g_Z[(size_t)((bbase + gb) * T_LEN) * C4 + rank * 128 + n2 * 4]);
    float4 zcb = __ldg((const float4*)
        &g_Z[(size_t)((bbase + gb) * T_LEN) * C4 + rank * 128 + n2 * 4 + 4]);
    float2 h0p = *(const float2*)&h_prev[(bbase + gb) * H_SZ + rank * 32 + n2];

    if (tid == 0) {
        mbar_init(mbar0, 1);
        mbar_init(mbar1, 1);
        mbar_expect_tx(mbar0, TXB);   // phase 0: h(0)
        mbar_expect_tx(mbar1, TXB);   // phase 0: h(1)
    }
    __syncthreads();
    CLUSTER_SYNC();   // barriers live before any remote traffic

    // slot offset of this thread's pair inside an h buffer (floats)
    const uint32_t slot = (uint32_t)(gb * HB_PITCH + rank * 32 + n2);

    // ---- publish h(0) straight to all 8 cluster CTAs -----------------------
#pragma unroll
    for (int p = 0; p < CLUSTER_N; p++) {
        uint32_t ra = mapa_u32(smbase + 4u * slot, (uint32_t)p);
        uint32_t rm = mapa_u32(mbar0, (uint32_t)p);
        st_async_f2(ra, h0p.x, h0p.y, rm);
    }

    for (int t = 0; t < T_LEN; t++) {
        const int par = t & 1;
        const uint32_t mb = par ? mbar1 : mbar0;

        // prefetch Z(t+1): overlaps the wait
        float4 zna = zca, znb = zcb;
        if (t + 1 < T_LEN) {
            const float* zp =
                &g_Z[(size_t)((bbase + gb) * T_LEN + t + 1) * C4 + rank * 128 + n2 * 4];
            zna = __ldg((const float4*)zp);
            znb = __ldg((const float4*)(zp + 4));
        }

        // wait: all 16KB of h(t) landed in hb[par]
        mbar_wait_cluster(mb, (uint32_t)((t >> 1) & 1));
        if (tid == 0) mbar_expect_tx(mb, TXB);   // re-arm for step t+2

        // ---- mma: P[16 x 128] over this warp's k-half ----------------------
        const float* hb = sm + par * HB_SZ;
        float acc[4][4];
#pragma unroll
        for (int nt = 0; nt < 4; nt++)
#pragma unroll
            for (int i = 0; i < 4; i++) acc[nt][i] = 0.f;

#pragma unroll
        for (int ks = 0; ks < 16; ks++) {
            int k0 = kh * 128 + ks * 8;
            const float* pa = &hb[lq * HB_PITCH + k0 + lr];
            unsigned a[4];
            a[0] = __float_as_uint(pa[0]);
            a[1] = __float_as_uint(pa[8 * HB_PITCH]);
            a[2] = __float_as_uint(pa[4]);
            a[3] = __float_as_uint(pa[8 * HB_PITCH + 4]);
            mma_tf32(acc[0], a, wr0[ks][0], wr1[ks][0]);
            mma_tf32(acc[1], a, wr0[ks][1], wr1[ks][1]);
            mma_tf32(acc[2], a, wr0[ks][2], wr1[ks][2]);
            mma_tf32(acc[3], a, wr0[ks][3], wr1[ks][3]);
        }

        // partials: pp[kh][b][col]
        {
            float* ppk = sm + PP_OFF + kh * PP_SZ;
#pragma unroll
            for (int nt = 0; nt < 4; nt++) {
                int c = wn * 32 + nt * 8 + lr * 2;
                *(float2*)&ppk[lq * PP_PITCH + c]       = make_float2(acc[nt][0], acc[nt][1]);
                *(float2*)&ppk[(lq + 8) * PP_PITCH + c] = make_float2(acc[nt][2], acc[nt][3]);
            }
        }
        __syncthreads();   // pp complete before gates read

        // ---- gates: adjacent unit pair (gb, n2), (gb, n2+1) ----------------
        const float* ppb0 = sm + PP_OFF + gb * PP_PITCH + n2 * 4;
        const float* ppb1 = ppb0 + PP_SZ;
        const float4 qa0 = *(const float4*)ppb0;
        const float4 qb0 = *(const float4*)(ppb0 + 4);
        const float4 qa1 = *(const float4*)ppb1;
        const float4 qb1 = *(const float4*)(ppb1 + 4);

        float hn0, hn1;
        {
            float p0 = qa0.x + qa1.x + zca.x;
            float p1 = qa0.y + qa1.y + zca.y;
            float p2 = qa0.z + qa1.z + zca.z;
            float p3 = qa0.w + qa1.w + zca.w;
            float f  = fast_sigmoid(p0);
            float ig = fast_sigmoid(p1);
            float o  = fast_sigmoid(p2);
            float g  = fast_tanh(p3);
            creg.x = f * creg.x + ig * g;
            hn0 = o * fast_tanh(creg.x);
        }
        {
            float p0 = qb0.x + qb1.x + zcb.x;
            float p1 = qb0.y + qb1.y + zcb.y;
            float p2 = qb0.z + qb1.z + zcb.z;
            float p3 = qb0.w + qb1.w + zcb.w;
            float f  = fast_sigmoid(p0);
            float ig = fast_sigmoid(p1);
            float o  = fast_sigmoid(p2);
            float g  = fast_tanh(p3);
            creg.y = f * creg.y + ig * g;
            hn1 = o * fast_tanh(creg.y);
        }
        zca = zna; zcb = znb;

        // ---- publish h(t+1) directly from registers (st.async) -------------
        if (t + 1 < T_LEN) {
            const int nb = (t + 1) & 1;
            const uint32_t nmb  = nb ? mbar1 : mbar0;
            const uint32_t base = smbase + 4u * ((uint32_t)nb * HB_SZ + slot);
#pragma unroll
            for (int p = 0; p < CLUSTER_N; p++) {
                uint32_t ra = mapa_u32(base, (uint32_t)p);
                uint32_t rm = mapa_u32(nmb, (uint32_t)p);
                st_async_f2(ra, hn0, hn1, rm);
            }
        }

        // off-critical-path outputs
        {
            size_t off = (size_t)((bbase + gb) * T_LEN + t) * H_SZ + rank * 32 + n2;
            *(float2*)&hseq[off] = make_float2(hn0, hn1);
            *(float2*)&cseq[off] = creg;
        }
    }
    CLUSTER_SYNC();   // no CTA exits while cluster smem may be in use
}

// ---------------- launch --------------------------------------------------
extern "C" void kernel_launch(void* const* d_in, const int* in_sizes, int n_in,
                              void* d_out, int out_size) {
    const float* x    = (const float*)d_in[0];
    const float* h0   = (const float*)d_in[1];
    const float* c0   = (const float*)d_in[2];
    const float* Win  = (const float*)d_in[3];
    const float* Wx   = (const float*)d_in[4];
    const float* Wh   = (const float*)d_in[5];
    const float* We   = (const float*)d_in[6];
    const float* bb   = (const float*)d_in[7];
    const float* Wout = (const float*)d_in[8];
    const float* bout = (const float*)d_in[9];

    float* out  = (float*)d_out;
    float* yhat = out;                                   // [B,T,D]
    float* hseq = out + (size_t)B_SZ * T_LEN * D_SZ;     // [B,T,H]
    float* cseq = hseq + (size_t)B_SZ * T_LEN * H_SZ;    // [B,T,H]

    float *pM2, *pbias2, *pZ;
    cudaGetSymbolAddress((void**)&pM2,    g_M2);
    cudaGetSymbolAddress((void**)&pbias2, g_bias2);
    cudaGetSymbolAddress((void**)&pZ,     g_Z);

    // phase 0: fold weights
    k_prepM<<<dim3(4, 256), 256>>>(Win, Wx, We, bb);
    k_prepW<<<dim3(4, 256), 256>>>(Wh, We);

    // phase A: Z = x * M2 + bias2      (65536 x 1024 x 256)
    k_gemm_bias<64><<<dim3(1024 / 64, 65536 / 128), 256>>>(
        x, pM2, pbias2, pZ, 1024, 256);

    // phase B: cluster recurrence, st.async exchange
    cudaFuncSetAttribute(k_recur, cudaFuncAttributeMaxDynamicSharedMemorySize,
                         SMEMB);
    k_recur<<<NRC, 256, SMEMB>>>(h0, c0, hseq, cseq);

    // phase C: y = h_seq * W_out + b_out   (65536 x 256 x 256)
    k_gemm_bias<64><<<dim3(256 / 64, 65536 / 128), 256>>>(
        hseq, Wout, bout, yhat, 256, 256);
}

// round 17
// speedup vs baseline: 2.2045x; 1.1605x over previous
#include <cuda_runtime.h>
#include <cuda_fp16.h>
#include <math.h>
#include <stdint.h>

#define T_LEN 1024
#define B_SZ  64
#define H_SZ  256
#define D_SZ  256
#define C4    1024          // 4*H, col = j*4 + k (gates of a neuron contiguous)

#define CLUSTER_N 8         // CTAs per cluster
#define N_CLUSTERS 4        // clusters (x16 batches each)
#define NRC (CLUSTER_N * N_CLUSTERS)   // 32 recurrent CTAs
#define BPC 16              // batches per cluster
#define TXB 8192            // bytes received per CTA per step (8 senders x 1KB)

// smem layout for k_recur (u32 units)
#define P32     132                       // u32 pitch of h rows [b][k/2]
#define HB32    (BPC * P32)               // 2112 u32 per h buffer (fp16 data)
#define PPF_OFF (2 * HB32)                // pp (f32) starts after 4224 u32
#define PP_PITCH 132
#define PP_SZ   (BPC * PP_PITCH)          // 2112 floats per k-half
#define MB_BYTE ((PPF_OFF + 2 * PP_SZ) * 4)   // 33792, 8B aligned
#define SMEMB   (MB_BYTE + 16)            // 33808 bytes

// ---------------- scratch (static device allocations only) ----------------
__device__ float g_M2[D_SZ * C4];            // folded x-projection  [d][col]
__device__ float g_bias2[C4];
__device__ float g_Wp[H_SZ * C4];            // folded recurrent (Wh - We), [k][col]
__device__ float g_Z[(size_t)B_SZ * T_LEN * C4];   // b-major: [b*T+t][1024]

// ---------------- ptx helpers ----------------------------------------------
__device__ __forceinline__ uint32_t smem_u32(const void* p) {
    uint32_t a;
    asm("{ .reg .u64 t; cvta.to.shared.u64 t, %1; cvt.u32.u64 %0, t; }"
        : "=r"(a) : "l"(p));
    return a;
}
__device__ __forceinline__ uint32_t mapa_u32(uint32_t laddr, uint32_t rank) {
    uint32_t r;
    asm("mapa.shared::cluster.u32 %0, %1, %2;" : "=r"(r) : "r"(laddr), "r"(rank));
    return r;
}
__device__ __forceinline__ void mbar_init(uint32_t mbar, uint32_t cnt) {
    asm volatile("mbarrier.init.shared.b64 [%0], %1;" :: "r"(mbar), "r"(cnt)
                 : "memory");
}
__device__ __forceinline__ void mbar_expect_tx(uint32_t mbar, uint32_t bytes) {
    asm volatile("mbarrier.arrive.expect_tx.shared.b64 _, [%0], %1;"
                 :: "r"(mbar), "r"(bytes) : "memory");
}
// remote DSMEM b32 store carrying its own tx-count to the remote mbarrier
__device__ __forceinline__ void st_async_b32(uint32_t raddr, uint32_t v,
                                             uint32_t rmbar) {
    asm volatile(
        "st.async.shared::cluster.mbarrier::complete_tx::bytes.b32 [%0], %1, [%2];"
        :: "r"(raddr), "r"(v), "r"(rmbar) : "memory");
}
__device__ __forceinline__ void mbar_wait_cluster(uint32_t mbar, uint32_t parity) {
    asm volatile(
        "{\n\t"
        ".reg .pred P;\n\t"
        "W%=:\n\t"
        "mbarrier.try_wait.parity.acquire.cluster.shared::cta.b64 P, [%0], %1, 0x989680;\n\t"
        "@P bra.uni D%=;\n\t"
        "bra.uni W%=;\n\t"
        "D%=:\n\t"
        "}"
        :: "r"(mbar), "r"(parity) : "memory");
}
#define CLUSTER_SYNC() do { \
    asm volatile("barrier.cluster.arrive.aligned;" ::: "memory"); \
    asm volatile("barrier.cluster.wait.aligned;" ::: "memory"); \
} while (0)

// fp16 mma: D[16x8] += A[16x16] * B[16x8], fp32 accumulate
__device__ __forceinline__ void mma_f16(float* c, const uint32_t* a,
                                        uint32_t b0, uint32_t b1) {
    asm volatile(
        "mma.sync.aligned.m16n8k16.row.col.f32.f16.f16.f32 "
        "{%0,%1,%2,%3}, {%4,%5,%6,%7}, {%8,%9}, {%0,%1,%2,%3};"
        : "+f"(c[0]), "+f"(c[1]), "+f"(c[2]), "+f"(c[3])
        : "r"(a[0]), "r"(a[1]), "r"(a[2]), "r"(a[3]), "r"(b0), "r"(b1));
}
__device__ __forceinline__ uint32_t pack_h2(float lo, float hi) {
    __half2 h = __floats2half2_rn(lo, hi);
    return *reinterpret_cast<uint32_t*>(&h);
}

__device__ __forceinline__ float fast_sigmoid(float x) {
    return 1.f / (1.f + __expf(-x));
}
__device__ __forceinline__ float fast_tanh(float x) {
    float xc = fminf(fmaxf(x, -30.f), 30.f);
    float t = __expf(-2.f * xc);
    return __fdividef(1.f - t, 1.f + t);
}

// ---------------- prep kernels --------------------------------------------
__global__ void k_prepM(const float* __restrict__ Win, const float* __restrict__ Wx,
                        const float* __restrict__ We, const float* __restrict__ b) {
    int k = blockIdx.x, d = blockIdx.y, j = threadIdx.x;
    float acc = Wx[(k * D_SZ + d) * H_SZ + j];
    const float* wrow = &Win[d * H_SZ];
#pragma unroll 8
    for (int e = 0; e < H_SZ; e++)
        acc = fmaf(__ldg(&wrow[e]), __ldg(&We[(k * H_SZ + e) * H_SZ + j]), acc);
    g_M2[d * C4 + j * 4 + k] = acc;
    if (d == 0) g_bias2[j * 4 + k] = b[k * H_SZ + j];
}

__global__ void k_prepW(const float* __restrict__ Wh, const float* __restrict__ We) {
    int k = blockIdx.x, h = blockIdx.y, j = threadIdx.x;
    int src = (k * H_SZ + h) * H_SZ + j;
    g_Wp[h * C4 + j * 4 + k] = Wh[src] - We[src];
}

// ---------------- tiled fp32 GEMM with bias (proven ~60% FFMA) -------------
template<int BN>
__global__ void __launch_bounds__(256) k_gemm_bias(
    const float* __restrict__ A, const float* __restrict__ Bm,
    const float* __restrict__ bias, float* __restrict__ Cm,
    int N, int K)
{
    const int BM = 128, BK = 16, TM = 8, TN = 4;
    __shared__ float As[BK][BM + 4];
    __shared__ float Bs[BK][BN + 4];

    int tid = threadIdx.x;
    int tx = tid % (BN / TN);
    int ty = tid / (BN / TN);
    int row0 = blockIdx.y * BM;
    int col0 = blockIdx.x * BN;

    float acc[TM][TN];
#pragma unroll
    for (int m = 0; m < TM; m++)
#pragma unroll
        for (int n = 0; n < TN; n++) acc[m][n] = 0.f;

    for (int k0 = 0; k0 < K; k0 += BK) {
#pragma unroll
        for (int i = tid; i < BM * (BK / 4); i += 256) {
            int r  = i >> 2;
            int c4 = i & 3;
            float4 v = *(const float4*)&A[(size_t)(row0 + r) * K + k0 + c4 * 4];
            As[c4 * 4 + 0][r] = v.x;
            As[c4 * 4 + 1][r] = v.y;
            As[c4 * 4 + 2][r] = v.z;
            As[c4 * 4 + 3][r] = v.w;
        }
#pragma unroll
        for (int i = tid; i < BK * (BN / 4); i += 256) {
            int r  = i / (BN / 4);
            int c4 = i % (BN / 4);
            *(float4*)&Bs[r][c4 * 4] =
                *(const float4*)&Bm[(size_t)(k0 + r) * N + col0 + c4 * 4];
        }
        __syncthreads();

#pragma unroll
        for (int k = 0; k < BK; k++) {
            float a[TM], bb[TN];
#pragma unroll
            for (int m = 0; m < TM; m++) a[m] = As[k][ty * TM + m];
#pragma unroll
            for (int n = 0; n < TN; n++) bb[n] = Bs[k][tx * TN + n];
#pragma unroll
            for (int m = 0; m < TM; m++)
#pragma unroll
                for (int n = 0; n < TN; n++)
                    acc[m][n] = fmaf(a[m], bb[n], acc[m][n]);
        }
        __syncthreads();
    }

    float4 bv = *(const float4*)&bias[col0 + tx * TN];
#pragma unroll
    for (int m = 0; m < TM; m++) {
        int r = row0 + ty * TM + m;
        float4 o;
        o.x = acc[m][0] + bv.x;
        o.y = acc[m][1] + bv.y;
        o.z = acc[m][2] + bv.z;
        o.w = acc[m][3] + bv.w;
        *(float4*)&Cm[(size_t)r * N + col0 + tx * TN] = o;
    }
}

// ---------------- phase B: cluster recurrence, fp16 exchange + fp16 mma ----
// 4 clusters x 8 CTAs; cluster owns 16 batches, CTA owns 128 gate-cols.
// h exchanged as packed half2 via st.async.b32 (8KB/CTA/step, halving the
// DSMEM producer-port cost); recurrent GEMM is m16n8k16 fp16 mma with fp32
// accumulate (32 mma/warp). c, gates, Z, outputs all stay fp32.
__global__ void __launch_bounds__(256, 1) __cluster_dims__(CLUSTER_N, 1, 1)
k_recur(const float* __restrict__ h_prev, const float* __restrict__ c_prev,
        float* __restrict__ hseq, float* __restrict__ cseq)
{
    extern __shared__ uint32_t smu[];
    float* pp = (float*)(smu + PPF_OFF);
    const uint32_t smbase = smem_u32(smu);
    const uint32_t mbar0  = smbase + MB_BYTE;
    const uint32_t mbar1  = mbar0 + 8;

    const int tid  = threadIdx.x;
    const int rank = blockIdx.x & (CLUSTER_N - 1);
    const int cid  = blockIdx.x >> 3;          // cluster id
    const int bbase = cid * BPC;               // first global batch
    const int lane = tid & 31;
    const int w    = tid >> 5;
    const int kh   = w >> 2;                   // k-half: k in [128kh, +128)
    const int wn   = w & 3;                    // n-quarter: local cols [32wn, +32)
    const int lq = lane >> 2;                  // 0..7
    const int lr = lane & 3;                   // 0..3

    // gate-unit mapping: thread owns (b, n2) and (b, n2+1) — adjacent pair
    const int gb = tid >> 4;                   // 0..15
    const int n2 = (tid & 15) * 2;             // 0,2,..,30

    // ---- Wp fragments in registers as packed fp16 pairs: 8 ks x 4 nt x 2 --
    uint32_t wb0[8][4], wb1[8][4];
#pragma unroll
    for (int ks = 0; ks < 8; ks++) {
        int k0 = kh * 128 + ks * 16;
#pragma unroll
        for (int nt = 0; nt < 4; nt++) {
            int gc = rank * 128 + wn * 32 + nt * 8 + lq;
            wb0[ks][nt] = pack_h2(g_Wp[(k0 + 2 * lr)     * C4 + gc],
                                  g_Wp[(k0 + 2 * lr + 1) * C4 + gc]);
            wb1[ks][nt] = pack_h2(g_Wp[(k0 + 2 * lr + 8) * C4 + gc],
                                  g_Wp[(k0 + 2 * lr + 9) * C4 + gc]);
        }
    }

    // per-thread state: c pair, current/next Z (8 floats each)
    float2 creg = *(const float2*)&c_prev[(bbase + gb) * H_SZ + rank * 32 + n2];
    float4 zca = __ldg((const float4*)
        &g_Z[(size_t)((bbase + gb) * T_LEN) * C4 + rank * 128 + n2 * 4]);
    float4 zcb = __ldg((const float4*)
        &g_Z[(size_t)((bbase + gb) * T_LEN) * C4 + rank * 128 + n2 * 4 + 4]);
    float2 h0p = *(const float2*)&h_prev[(bbase + gb) * H_SZ + rank * 32 + n2];

    if (tid == 0) {
        mbar_init(mbar0, 1);
        mbar_init(mbar1, 1);
        mbar_expect_tx(mbar0, TXB);   // phase 0: h(0)
        mbar_expect_tx(mbar1, TXB);   // phase 0: h(1)
    }
    __syncthreads();
    CLUSTER_SYNC();   // barriers live before any remote traffic

    // u32 slot of this thread's half2 inside an h buffer
    const uint32_t slot = (uint32_t)(gb * P32 + rank * 16 + (n2 >> 1));

    // ---- publish h(0) straight to all 8 cluster CTAs -----------------------
    {
        uint32_t v = pack_h2(h0p.x, h0p.y);
#pragma unroll
        for (int p = 0; p < CLUSTER_N; p++) {
            uint32_t ra = mapa_u32(smbase + 4u * slot, (uint32_t)p);
            uint32_t rm = mapa_u32(mbar0, (uint32_t)p);
            st_async_b32(ra, v, rm);
        }
    }

    for (int t = 0; t < T_LEN; t++) {
        const int par = t & 1;
        const uint32_t mb = par ? mbar1 : mbar0;

        // prefetch Z(t+1): overlaps the wait
        float4 zna = zca, znb = zcb;
        if (t + 1 < T_LEN) {
            const float* zp =
                &g_Z[(size_t)((bbase + gb) * T_LEN + t + 1) * C4 + rank * 128 + n2 * 4];
            zna = __ldg((const float4*)zp);
            znb = __ldg((const float4*)(zp + 4));
        }

        // wait: all 8KB of h(t) landed in hb[par]
        mbar_wait_cluster(mb, (uint32_t)((t >> 1) & 1));
        if (tid == 0) mbar_expect_tx(mb, TXB);   // re-arm for step t+2

        // ---- mma: P[16 x 128] over this warp's k-half (fp16, k16) ----------
        const uint32_t* hb = smu + par * HB32;
        float acc[4][4];
#pragma unroll
        for (int nt = 0; nt < 4; nt++)
#pragma unroll
            for (int i = 0; i < 4; i++) acc[nt][i] = 0.f;

#pragma unroll
        for (int ks = 0; ks < 8; ks++) {
            int kb = kh * 64 + ks * 8;          // u32 index of k0/2
            const uint32_t* pa = &hb[lq * P32 + kb + lr];
            uint32_t a[4];
            a[0] = pa[0];
            a[1] = pa[8 * P32];
            a[2] = pa[4];
            a[3] = pa[8 * P32 + 4];
            mma_f16(acc[0], a, wb0[ks][0], wb1[ks][0]);
            mma_f16(acc[1], a, wb0[ks][1], wb1[ks][1]);
            mma_f16(acc[2], a, wb0[ks][2], wb1[ks][2]);
            mma_f16(acc[3], a, wb0[ks][3], wb1[ks][3]);
        }

        // partials: pp[kh][b][col]
        {
            float* ppk = pp + kh * PP_SZ;
#pragma unroll
            for (int nt = 0; nt < 4; nt++) {
                int c = wn * 32 + nt * 8 + lr * 2;
                *(float2*)&ppk[lq * PP_PITCH + c]       = make_float2(acc[nt][0], acc[nt][1]);
                *(float2*)&ppk[(lq + 8) * PP_PITCH + c] = make_float2(acc[nt][2], acc[nt][3]);
            }
        }
        __syncthreads();   // pp complete before gates read

        // ---- gates: adjacent unit pair (gb, n2), (gb, n2+1) ----------------
        const float* ppb0 = pp + gb * PP_PITCH + n2 * 4;
        const float* ppb1 = ppb0 + PP_SZ;
        const float4 qa0 = *(const float4*)ppb0;
        const float4 qb0 = *(const float4*)(ppb0 + 4);
        const float4 qa1 = *(const float4*)ppb1;
        const float4 qb1 = *(const float4*)(ppb1 + 4);

        float hn0, hn1;
        {
            float p0 = qa0.x + qa1.x + zca.x;
            float p1 = qa0.y + qa1.y + zca.y;
            float p2 = qa0.z + qa1.z + zca.z;
            float p3 = qa0.w + qa1.w + zca.w;
            float f  = fast_sigmoid(p0);
            float ig = fast_sigmoid(p1);
            float o  = fast_sigmoid(p2);
            float g  = fast_tanh(p3);
            creg.x = f * creg.x + ig * g;
            hn0 = o * fast_tanh(creg.x);
        }
        {
            float p0 = qb0.x + qb1.x + zcb.x;
            float p1 = qb0.y + qb1.y + zcb.y;
            float p2 = qb0.z + qb1.z + zcb.z;
            float p3 = qb0.w + qb1.w + zcb.w;
            float f  = fast_sigmoid(p0);
            float ig = fast_sigmoid(p1);
            float o  = fast_sigmoid(p2);
            float g  = fast_tanh(p3);
            creg.y = f * creg.y + ig * g;
            hn1 = o * fast_tanh(creg.y);
        }
        zca = zna; zcb = znb;

        // ---- publish h(t+1) directly from registers (st.async.b32) ---------
        if (t + 1 < T_LEN) {
            const int nb = (t + 1) & 1;
            const uint32_t nmb  = nb ? mbar1 : mbar0;
            const uint32_t base = smbase + 4u * ((uint32_t)nb * HB32 + slot);
            uint32_t v = pack_h2(hn0, hn1);
#pragma unroll
            for (int p = 0; p < CLUSTER_N; p++) {
                uint32_t ra = mapa_u32(base, (uint32_t)p);
                uint32_t rm = mapa_u32(nmb, (uint32_t)p);
                st_async_b32(ra, v, rm);
            }
        }

        // off-critical-path outputs
        {
            size_t off = (size_t)((bbase + gb) * T_LEN + t) * H_SZ + rank * 32 + n2;
            *(float2*)&hseq[off] = make_float2(hn0, hn1);
            *(float2*)&cseq[off] = creg;
        }
    }
    CLUSTER_SYNC();   // no CTA exits while cluster smem may be in use
}

// ---------------- launch --------------------------------------------------
extern "C" void kernel_launch(void* const* d_in, const int* in_sizes, int n_in,
                              void* d_out, int out_size) {
    const float* x    = (const float*)d_in[0];
    const float* h0   = (const float*)d_in[1];
    const float* c0   = (const float*)d_in[2];
    const float* Win  = (const float*)d_in[3];
    const float* Wx   = (const float*)d_in[4];
    const float* Wh   = (const float*)d_in[5];
    const float* We   = (const float*)d_in[6];
    const float* bb   = (const float*)d_in[7];
    const float* Wout = (const float*)d_in[8];
    const float* bout = (const float*)d_in[9];

    float* out  = (float*)d_out;
    float* yhat = out;                                   // [B,T,D]
    float* hseq = out + (size_t)B_SZ * T_LEN * D_SZ;     // [B,T,H]
    float* cseq = hseq + (size_t)B_SZ * T_LEN * H_SZ;    // [B,T,H]

    float *pM2, *pbias2, *pZ;
    cudaGetSymbolAddress((void**)&pM2,    g_M2);
    cudaGetSymbolAddress((void**)&pbias2, g_bias2);
    cudaGetSymbolAddress((void**)&pZ,     g_Z);

    // phase 0: fold weights
    k_prepM<<<dim3(4, 256), 256>>>(Win, Wx, We, bb);
    k_prepW<<<dim3(4, 256), 256>>>(Wh, We);

    // phase A: Z = x * M2 + bias2      (65536 x 1024 x 256)
    k_gemm_bias<64><<<dim3(1024 / 64, 65536 / 128), 256>>>(
        x, pM2, pbias2, pZ, 1024, 256);

    // phase B: cluster recurrence, fp16 st.async exchange + fp16 mma
    cudaFuncSetAttribute(k_recur, cudaFuncAttributeMaxDynamicSharedMemorySize,
                         SMEMB);
    k_recur<<<NRC, 256, SMEMB>>>(h0, c0, hseq, cseq);

    // phase C: y = h_seq * W_out + b_out   (65536 x 256 x 256)
    k_gemm_bias<64><<<dim3(256 / 64, 65536 / 128), 256>>>(
        hseq, Wout, bout, yhat, 256, 256);
}